// round 11
// baseline (speedup 1.0000x reference)
#include <cuda_runtime.h>
#include <cuda_fp16.h>
#include <cstdint>

#define BATCH 16
#define CCH   512
#define NPIX  4096
#define NTOT  ((size_t)BATCH * CCH * NPIX)

// scratch
__device__ float  g_energy[(size_t)BATCH * CCH * CCH];   // 16 MB fp32 energy
__device__ __half g_attn  [(size_t)BATCH * CCH * CCH];   // 8 MB fp16 attention
__device__ __half g_qh[NTOT];                            // 64 MB: rn(q)
__device__ __half g_ql[NTOT];                            // 64 MB: rn(q - qh)

// ---------------------------------------------------------------------------
// PTX helpers (base-ISA sm_75/80 ops, legal under compute_103)
// ---------------------------------------------------------------------------
__device__ __forceinline__ uint32_t smem_u32(const void* p) {
    uint32_t a;
    asm("{ .reg .u64 t; cvta.to.shared.u64 t, %1; cvt.u32.u64 %0, t; }" : "=r"(a) : "l"(p));
    return a;
}
__device__ __forceinline__ void ldm_x4(uint32_t* r, uint32_t addr) {
    asm volatile("ldmatrix.sync.aligned.m8n8.x4.shared.b16 {%0,%1,%2,%3}, [%4];"
        : "=r"(r[0]), "=r"(r[1]), "=r"(r[2]), "=r"(r[3]) : "r"(addr));
}
__device__ __forceinline__ void ldm_x4_t(uint32_t* r, uint32_t addr) {
    asm volatile("ldmatrix.sync.aligned.m8n8.x4.trans.shared.b16 {%0,%1,%2,%3}, [%4];"
        : "=r"(r[0]), "=r"(r[1]), "=r"(r[2]), "=r"(r[3]) : "r"(addr));
}
__device__ __forceinline__ void mma16(float* d, const uint32_t* a, const uint32_t* b) {
    asm volatile(
        "mma.sync.aligned.m16n8k16.row.col.f32.f16.f16.f32 "
        "{%0,%1,%2,%3}, {%4,%5,%6,%7}, {%8,%9}, {%0,%1,%2,%3};"
        : "+f"(d[0]), "+f"(d[1]), "+f"(d[2]), "+f"(d[3])
        : "r"(a[0]), "r"(a[1]), "r"(a[2]), "r"(a[3]), "r"(b[0]), "r"(b[1]));
}
__device__ __forceinline__ void cp16(uint32_t saddr, const void* g) {
    asm volatile("cp.async.cg.shared.global [%0], [%1], 16;" :: "r"(saddr), "l"(g) : "memory");
}
#define CP_COMMIT() asm volatile("cp.async.commit_group;" ::: "memory")
#define CP_WAIT(n)  asm volatile("cp.async.wait_group %0;" :: "n"(n) : "memory")

// ---------------------------------------------------------------------------
// Kernel 0: split q -> qh (rn fp16) + ql (rn residual fp16)
// ---------------------------------------------------------------------------
__global__ __launch_bounds__(256) void split_kernel(const float* __restrict__ x)
{
    size_t i = ((size_t)blockIdx.x * 256 + threadIdx.x) * 4;
    float4 v = *(const float4*)(x + i);
    __half2 h0 = __floats2half2_rn(v.x, v.y);
    __half2 h1 = __floats2half2_rn(v.z, v.w);
    float2 f0 = __half22float2(h0), f1 = __half22float2(h1);
    __half2 l0 = __floats2half2_rn(v.x - f0.x, v.y - f0.y);
    __half2 l1 = __floats2half2_rn(v.z - f1.x, v.w - f1.y);
    *(uint2*)(g_qh + i) = make_uint2(*(uint32_t*)&h0, *(uint32_t*)&h1);
    *(uint2*)(g_ql + i) = make_uint2(*(uint32_t*)&l0, *(uint32_t*)&l1);
}

// ---------------------------------------------------------------------------
// Kernel 1: energy[b] = q qᵀ (3-pass fp16: hh + hl + lh), symmetric 64x64 blocks.
// 128 thr (4 warps 2x2, warp 32x32), BK=64, cp.async double-buffer, ldmatrix.
// Tiles: 64 rows x 64 fp16, row stride 72 fp16 (144 B = 9*16B, conflict-free).
// ---------------------------------------------------------------------------
#define ERS_B   144                     // row stride bytes
#define ETILE_B (64 * ERS_B)            // 9216 B per tile
#define ESTAGE_B (4 * ETILE_B)          // AH|AL|BH|BL = 36864 B
#define ESMEM_TOTAL (2 * ESTAGE_B)      // 73728 B

__global__ __launch_bounds__(128) void energy_kernel()
{
    extern __shared__ __align__(256) char smem[];
    const uint32_t sbase = smem_u32(smem);
    const int tid = threadIdx.x, lane = tid & 31, wid = tid >> 5;
    const int b = blockIdx.y;

    int bi = 0, t = blockIdx.x, rowlen = 8;
    while (t >= rowlen) { t -= rowlen; bi++; rowlen--; }
    const int bj = bi + t;
    const int m0 = bi * 64, n0 = bj * 64;

    const __half* qh = g_qh + (size_t)b * CCH * NPIX;
    const __half* ql = g_ql + (size_t)b * CCH * NPIX;

    const int wm = (wid >> 1) * 32, wn = (wid & 1) * 32;
    const int qm = lane >> 2, qp = lane & 3;

    float acc[2][4][4];
#pragma unroll
    for (int i = 0; i < 2; i++)
#pragma unroll
        for (int j = 0; j < 4; j++)
#pragma unroll
            for (int k = 0; k < 4; k++) acc[i][j][k] = 0.f;

    // copy slots: per tile 64 rows x 8 16B-chunks = 512; 128 thr -> 4/thread
    const int er = tid >> 1;             // row 0..63
    const int ev = (tid & 1) * 4;        // first chunk (of 4 consecutive)

    // ldmatrix lane addressing
    const int aro = lane & 15, akq = (lane >> 4) * 16;
    const int bro = (lane & 7) + 8 * (lane >> 4);
    const int bkq = ((lane >> 3) & 1) * 16;

#define E_ISSUE(S, K0)                                                            \
    {                                                                             \
        const uint32_t tb = sbase + (S) * ESTAGE_B;                               \
        const __half* gA = qh + (size_t)(m0 + er) * NPIX + (K0);                  \
        const __half* gAl = ql + (size_t)(m0 + er) * NPIX + (K0);                 \
        const __half* gB = qh + (size_t)(n0 + er) * NPIX + (K0);                  \
        const __half* gBl = ql + (size_t)(n0 + er) * NPIX + (K0);                 \
        const uint32_t ro = tb + er * ERS_B + ev * 16;                            \
        _Pragma("unroll")                                                         \
        for (int c = 0; c < 4; c++) {                                             \
            cp16(ro + c * 16,                 gA  + (ev + c) * 8);                \
            cp16(ro + ETILE_B + c * 16,       gAl + (ev + c) * 8);                \
            cp16(ro + 2 * ETILE_B + c * 16,   gB  + (ev + c) * 8);                \
            cp16(ro + 3 * ETILE_B + c * 16,   gBl + (ev + c) * 8);                \
        }                                                                         \
        CP_COMMIT();                                                              \
    }

    E_ISSUE(0, 0);
    int s = 0;
    constexpr int NCH = NPIX / 64;   // 64
    for (int it = 0; it < NCH; ++it) {
        if (it + 1 < NCH) { E_ISSUE(s ^ 1, (it + 1) * 64); CP_WAIT(1); }
        else              { CP_WAIT(0); }
        __syncthreads();
        const uint32_t AH = sbase + s * ESTAGE_B;
        const uint32_t BH = AH + 2 * ETILE_B;
#pragma unroll
        for (int sl = 0; sl < 4; sl++) {
            uint32_t ah[2][4], al[2][4], bh[2][4], bl[2][4];
#pragma unroll
            for (int i = 0; i < 2; i++) {
                uint32_t ad = AH + (wm + i * 16 + aro) * ERS_B + sl * 32 + akq;
                ldm_x4(ah[i], ad);
                ldm_x4(al[i], ad + ETILE_B);
            }
#pragma unroll
            for (int jj = 0; jj < 2; jj++) {
                uint32_t bd = BH + (wn + jj * 16 + bro) * ERS_B + sl * 32 + bkq;
                ldm_x4(bh[jj], bd);
                ldm_x4(bl[jj], bd + ETILE_B);
            }
#pragma unroll
            for (int i = 0; i < 2; i++)
#pragma unroll
                for (int jj = 0; jj < 2; jj++) {
                    mma16(acc[i][2 * jj],     ah[i], bh[jj]);
                    mma16(acc[i][2 * jj + 1], ah[i], bh[jj] + 2);
                }
#pragma unroll
            for (int i = 0; i < 2; i++)
#pragma unroll
                for (int jj = 0; jj < 2; jj++) {
                    mma16(acc[i][2 * jj],     ah[i], bl[jj]);
                    mma16(acc[i][2 * jj + 1], ah[i], bl[jj] + 2);
                }
#pragma unroll
            for (int i = 0; i < 2; i++)
#pragma unroll
                for (int jj = 0; jj < 2; jj++) {
                    mma16(acc[i][2 * jj],     al[i], bh[jj]);
                    mma16(acc[i][2 * jj + 1], al[i], bh[jj] + 2);
                }
        }
        __syncthreads();
        s ^= 1;
    }

    float* E = g_energy + (size_t)b * CCH * CCH;
    const bool mir = (bi != bj);
#pragma unroll
    for (int i = 0; i < 2; i++)
#pragma unroll
        for (int j = 0; j < 4; j++) {
            const int m = m0 + wm + i * 16 + qm;
            const int n = n0 + wn + j * 8 + qp * 2;
            float2 v0 = make_float2(acc[i][j][0], acc[i][j][1]);
            float2 v1 = make_float2(acc[i][j][2], acc[i][j][3]);
            *(float2*)&E[(size_t)m * CCH + n]       = v0;
            *(float2*)&E[(size_t)(m + 8) * CCH + n] = v1;
            if (mir) {
                E[(size_t)n * CCH + m]           = v0.x;
                E[(size_t)(n + 1) * CCH + m]     = v0.y;
                E[(size_t)n * CCH + m + 8]       = v1.x;
                E[(size_t)(n + 1) * CCH + m + 8] = v1.y;
            }
        }
}

// ---------------------------------------------------------------------------
// Kernel 2: softmax of exp(rowmin - e)/sum, write fp16 attention
// ---------------------------------------------------------------------------
__global__ __launch_bounds__(256) void softmax_kernel()
{
    const int row  = blockIdx.x * 8 + (threadIdx.x >> 5);
    const int lane = threadIdx.x & 31;
    const float* e = g_energy + (size_t)row * CCH;
    __half* a = g_attn + (size_t)row * CCH;

    float v[16];
    float mn = 3.4e38f;
#pragma unroll
    for (int i = 0; i < 16; i++) { v[i] = e[lane + i * 32]; mn = fminf(mn, v[i]); }
#pragma unroll
    for (int o = 16; o > 0; o >>= 1)
        mn = fminf(mn, __shfl_xor_sync(0xffffffffu, mn, o));
    float s = 0.f;
#pragma unroll
    for (int i = 0; i < 16; i++) { v[i] = expf(mn - v[i]); s += v[i]; }
#pragma unroll
    for (int o = 16; o > 0; o >>= 1)
        s += __shfl_xor_sync(0xffffffffu, s, o);
    const float r = 1.0f / s;
#pragma unroll
    for (int i = 0; i < 16; i++) a[lane + i * 32] = __float2half_rn(v[i] * r);
}

// ---------------------------------------------------------------------------
// Kernel 3: y[b] = gamma * (attn[b] @ q[b]) + x[b]   (fp16 1-pass)
// A = g_attn [128 m x 64 k] row-major (stride 72 fp16); B = qh [64 k x 128 n]
// k-major (stride 136 fp16, ldmatrix.trans). 512 thr, warps 4x4, warp 32x32.
// BK=64 double-buffered.
// ---------------------------------------------------------------------------
#define OA_RS_B 144
#define OA_TILE_B (128 * OA_RS_B)        // 18432 B
#define OB_RS_B  272                     // 136 fp16
#define OB_TILE_B (64 * OB_RS_B)         // 17408 B
#define OSTAGE_B (OA_TILE_B + OB_TILE_B) // 35840 B
#define OSMEM_TOTAL (2 * OSTAGE_B)       // 71680 B

__global__ __launch_bounds__(512) void out_kernel(const float* __restrict__ x,
                                                  const float* __restrict__ gamma,
                                                  float* __restrict__ out)
{
    extern __shared__ __align__(256) char smem[];
    const uint32_t sbase = smem_u32(smem);
    const int tid = threadIdx.x, lane = tid & 31, wid = tid >> 5;
    const int b = blockIdx.z;
    const __half* A = g_attn + (size_t)b * CCH * CCH;
    const __half* qh = g_qh + (size_t)b * CCH * NPIX;
    const int m0 = blockIdx.y * 128;
    const int n0 = blockIdx.x * 128;

    const int wm = (wid >> 2) * 32, wn = (wid & 3) * 32;
    const int qm = lane >> 2, qp = lane & 3;

    // copy slots: A 128 rows x 8 chunks = 1024 (2/thread); B 64 rows x 16 = 1024
    const int acr = tid >> 2, acv = (tid & 3) * 2;
    const int bcr = tid >> 3, bcv = (tid & 7) * 2;

    const int aro = lane & 15, akq = (lane >> 4) * 16;
    const int bro = (lane & 7) + 8 * ((lane >> 3) & 1);
    const int bco = 8 * (lane >> 4);

    float acc[2][4][4];
#pragma unroll
    for (int i = 0; i < 2; i++)
#pragma unroll
        for (int j = 0; j < 4; j++)
#pragma unroll
            for (int k = 0; k < 4; k++) acc[i][j][k] = 0.f;

#define O_ISSUE(S, K0)                                                            \
    {                                                                             \
        const uint32_t tb = sbase + (S) * OSTAGE_B;                               \
        const __half* gA = A + (size_t)(m0 + acr) * CCH + (K0);                   \
        const __half* gB = qh + (size_t)((K0) + bcr) * NPIX + n0;                 \
        _Pragma("unroll")                                                         \
        for (int c = 0; c < 2; c++) {                                             \
            cp16(tb + acr * OA_RS_B + (acv + c) * 16, gA + (acv + c) * 8);        \
            cp16(tb + OA_TILE_B + bcr * OB_RS_B + (bcv + c) * 16,                 \
                 gB + (bcv + c) * 8);                                             \
        }                                                                         \
        CP_COMMIT();                                                              \
    }

    O_ISSUE(0, 0);
    int s = 0;
    constexpr int NCH = CCH / 64;   // 8
    for (int it = 0; it < NCH; ++it) {
        if (it + 1 < NCH) { O_ISSUE(s ^ 1, (it + 1) * 64); CP_WAIT(1); }
        else              { CP_WAIT(0); }
        __syncthreads();
        const uint32_t AB = sbase + s * OSTAGE_B;
        const uint32_t BB = AB + OA_TILE_B;
#pragma unroll
        for (int sl = 0; sl < 4; sl++) {
            uint32_t af[2][4], bf[2][4];
#pragma unroll
            for (int i = 0; i < 2; i++)
                ldm_x4(af[i], AB + (wm + i * 16 + aro) * OA_RS_B + sl * 32 + akq);
#pragma unroll
            for (int jj = 0; jj < 2; jj++)
                ldm_x4_t(bf[jj], BB + (sl * 16 + bro) * OB_RS_B
                                    + (wn + jj * 16 + bco) * 2);
#pragma unroll
            for (int i = 0; i < 2; i++)
#pragma unroll
                for (int jj = 0; jj < 2; jj++) {
                    mma16(acc[i][2 * jj],     af[i], bf[jj]);
                    mma16(acc[i][2 * jj + 1], af[i], bf[jj] + 2);
                }
        }
        __syncthreads();
        s ^= 1;
    }

    const float g = *gamma;
#pragma unroll
    for (int i = 0; i < 2; i++)
#pragma unroll
        for (int j = 0; j < 4; j++) {
            const int m = m0 + wm + i * 16 + qm;
            const int n = n0 + wn + j * 8 + qp * 2;
            {
                const size_t p = (size_t)(b * CCH + m) * NPIX + n;
                float2 xv = *(const float2*)(x + p);
                float2 o;
                o.x = fmaf(g, acc[i][j][0], xv.x);
                o.y = fmaf(g, acc[i][j][1], xv.y);
                *(float2*)(out + p) = o;
            }
            {
                const size_t p = (size_t)(b * CCH + m + 8) * NPIX + n;
                float2 xv = *(const float2*)(x + p);
                float2 o;
                o.x = fmaf(g, acc[i][j][2], xv.x);
                o.y = fmaf(g, acc[i][j][3], xv.y);
                *(float2*)(out + p) = o;
            }
        }
}

// ---------------------------------------------------------------------------
extern "C" void kernel_launch(void* const* d_in, const int* in_sizes, int n_in,
                              void* d_out, int out_size)
{
    const float* x     = (const float*)d_in[0];
    const float* gamma = (const float*)d_in[1];
    float* out = (float*)d_out;

    cudaFuncSetAttribute(energy_kernel,
                         cudaFuncAttributeMaxDynamicSharedMemorySize, ESMEM_TOTAL);
    cudaFuncSetAttribute(out_kernel,
                         cudaFuncAttributeMaxDynamicSharedMemorySize, OSMEM_TOTAL);

    split_kernel<<<(unsigned)(NTOT / 4 / 256), 256>>>(x);
    energy_kernel<<<dim3(36, BATCH), 128, ESMEM_TOTAL>>>();
    softmax_kernel<<<(BATCH * CCH) / 8, 256>>>();
    out_kernel<<<dim3(NPIX / 128, CCH / 128, BATCH), 512, OSMEM_TOTAL>>>(x, gamma, out);
}

// round 12
// speedup vs baseline: 1.3314x; 1.3314x over previous
#include <cuda_runtime.h>
#include <cuda_fp16.h>
#include <cstdint>

#define BATCH 16
#define CCH   512
#define NPIX  4096
#define NTOT  ((size_t)BATCH * CCH * NPIX)

// scratch
__device__ float  g_energy[(size_t)BATCH * CCH * CCH];   // 16 MB fp32 energy
__device__ __half g_attn  [(size_t)BATCH * CCH * CCH];   // 8 MB fp16 attention
__device__ __half g_qh[NTOT];                            // 64 MB: rn(q)
__device__ __half g_ql[NTOT];                            // 64 MB: rn(q - qh)

// ---------------------------------------------------------------------------
// PTX helpers (base-ISA sm_75/80 ops, legal under compute_103)
// ---------------------------------------------------------------------------
__device__ __forceinline__ uint32_t smem_u32(const void* p) {
    uint32_t a;
    asm("{ .reg .u64 t; cvta.to.shared.u64 t, %1; cvt.u32.u64 %0, t; }" : "=r"(a) : "l"(p));
    return a;
}
__device__ __forceinline__ void ldm_x4(uint32_t* r, uint32_t addr) {
    asm volatile("ldmatrix.sync.aligned.m8n8.x4.shared.b16 {%0,%1,%2,%3}, [%4];"
        : "=r"(r[0]), "=r"(r[1]), "=r"(r[2]), "=r"(r[3]) : "r"(addr));
}
__device__ __forceinline__ void ldm_x4_t(uint32_t* r, uint32_t addr) {
    asm volatile("ldmatrix.sync.aligned.m8n8.x4.trans.shared.b16 {%0,%1,%2,%3}, [%4];"
        : "=r"(r[0]), "=r"(r[1]), "=r"(r[2]), "=r"(r[3]) : "r"(addr));
}
__device__ __forceinline__ void mma16(float* d, const uint32_t* a, const uint32_t* b) {
    asm volatile(
        "mma.sync.aligned.m16n8k16.row.col.f32.f16.f16.f32 "
        "{%0,%1,%2,%3}, {%4,%5,%6,%7}, {%8,%9}, {%0,%1,%2,%3};"
        : "+f"(d[0]), "+f"(d[1]), "+f"(d[2]), "+f"(d[3])
        : "r"(a[0]), "r"(a[1]), "r"(a[2]), "r"(a[3]), "r"(b[0]), "r"(b[1]));
}
__device__ __forceinline__ void cp16(uint32_t saddr, const void* g) {
    asm volatile("cp.async.cg.shared.global [%0], [%1], 16;" :: "r"(saddr), "l"(g) : "memory");
}
#define CP_COMMIT() asm volatile("cp.async.commit_group;" ::: "memory")
#define CP_WAIT(n)  asm volatile("cp.async.wait_group %0;" :: "n"(n) : "memory")

// ---------------------------------------------------------------------------
// Kernel 0: split q -> qh (rn fp16) + ql (rn residual fp16)
// ---------------------------------------------------------------------------
__global__ __launch_bounds__(256) void split_kernel(const float* __restrict__ x)
{
    size_t i = ((size_t)blockIdx.x * 256 + threadIdx.x) * 4;
    float4 v = *(const float4*)(x + i);
    __half2 h0 = __floats2half2_rn(v.x, v.y);
    __half2 h1 = __floats2half2_rn(v.z, v.w);
    float2 f0 = __half22float2(h0), f1 = __half22float2(h1);
    __half2 l0 = __floats2half2_rn(v.x - f0.x, v.y - f0.y);
    __half2 l1 = __floats2half2_rn(v.z - f1.x, v.w - f1.y);
    *(uint2*)(g_qh + i) = make_uint2(*(uint32_t*)&h0, *(uint32_t*)&h1);
    *(uint2*)(g_ql + i) = make_uint2(*(uint32_t*)&l0, *(uint32_t*)&l1);
}

// ---------------------------------------------------------------------------
// Kernel 1: energy[b] = q qᵀ (3-pass fp16: hh + hl + lh), symmetric 64x64 blocks.
// 128 thr (4 warps 2x2, warp 32x32), BK=32, cp.async double-buffer, ldmatrix.
// (Round-10 proven config: 40 KB static smem, 5 CTAs/SM.)
// ---------------------------------------------------------------------------
#define ERS_B  80                       // row stride bytes
#define ETILE_B (64 * ERS_B)            // 5120 B per tile
#define ESTAGE_B (4 * ETILE_B)          // AH|AL|BH|BL = 20480 B

__global__ __launch_bounds__(128) void energy_kernel()
{
    __shared__ __align__(256) char smem[2 * ESTAGE_B];   // 40 KB
    const uint32_t sbase = smem_u32(smem);
    const int tid = threadIdx.x, lane = tid & 31, wid = tid >> 5;
    const int b = blockIdx.y;

    int bi = 0, t = blockIdx.x, rowlen = 8;
    while (t >= rowlen) { t -= rowlen; bi++; rowlen--; }
    const int bj = bi + t;
    const int m0 = bi * 64, n0 = bj * 64;

    const __half* qh = g_qh + (size_t)b * CCH * NPIX;
    const __half* ql = g_ql + (size_t)b * CCH * NPIX;

    const int wm = (wid >> 1) * 32, wn = (wid & 1) * 32;
    const int qm = lane >> 2, qp = lane & 3;

    float acc[2][4][4];
#pragma unroll
    for (int i = 0; i < 2; i++)
#pragma unroll
        for (int j = 0; j < 4; j++)
#pragma unroll
            for (int k = 0; k < 4; k++) acc[i][j][k] = 0.f;

    // per-thread copy slots: per tile 256 16B-chunks (64 rows x 4), 2 per thread
    const int cr0 = tid >> 2, cv0 = tid & 3;
    const int cr1 = (tid + 128) >> 2, cv1 = tid & 3;

    const int aro = lane & 15, akq = (lane >> 4) * 16;
    const int bro = (lane & 7) + 8 * (lane >> 4);
    const int bkq = ((lane >> 3) & 1) * 16;

#define E_ISSUE(S, K0)                                                           \
    {                                                                            \
        const uint32_t tb = sbase + (S) * ESTAGE_B;                              \
        const __half* sA0 = qh + (size_t)(m0 + cr0) * NPIX + (K0);               \
        const __half* sA1 = qh + (size_t)(m0 + cr1) * NPIX + (K0);               \
        cp16(tb + cr0 * ERS_B + cv0 * 16, sA0 + cv0 * 8);                        \
        cp16(tb + cr1 * ERS_B + cv1 * 16, sA1 + cv1 * 8);                        \
        const __half* lA0 = ql + (size_t)(m0 + cr0) * NPIX + (K0);               \
        const __half* lA1 = ql + (size_t)(m0 + cr1) * NPIX + (K0);               \
        cp16(tb + ETILE_B + cr0 * ERS_B + cv0 * 16, lA0 + cv0 * 8);              \
        cp16(tb + ETILE_B + cr1 * ERS_B + cv1 * 16, lA1 + cv1 * 8);              \
        const __half* sB0 = qh + (size_t)(n0 + cr0) * NPIX + (K0);               \
        const __half* sB1 = qh + (size_t)(n0 + cr1) * NPIX + (K0);               \
        cp16(tb + 2 * ETILE_B + cr0 * ERS_B + cv0 * 16, sB0 + cv0 * 8);          \
        cp16(tb + 2 * ETILE_B + cr1 * ERS_B + cv1 * 16, sB1 + cv1 * 8);          \
        const __half* lB0 = ql + (size_t)(n0 + cr0) * NPIX + (K0);               \
        const __half* lB1 = ql + (size_t)(n0 + cr1) * NPIX + (K0);               \
        cp16(tb + 3 * ETILE_B + cr0 * ERS_B + cv0 * 16, lB0 + cv0 * 8);          \
        cp16(tb + 3 * ETILE_B + cr1 * ERS_B + cv1 * 16, lB1 + cv1 * 8);          \
        CP_COMMIT();                                                             \
    }

    E_ISSUE(0, 0);
    int s = 0;
    constexpr int NCH = NPIX / 32;   // 128
    for (int it = 0; it < NCH; ++it) {
        if (it + 1 < NCH) { E_ISSUE(s ^ 1, (it + 1) * 32); CP_WAIT(1); }
        else              { CP_WAIT(0); }
        __syncthreads();
        const uint32_t AH = sbase + s * ESTAGE_B;
        const uint32_t BH = AH + 2 * ETILE_B;
#pragma unroll
        for (int sl = 0; sl < 2; sl++) {
            uint32_t ah[2][4], al[2][4], bh[2][4], bl[2][4];
#pragma unroll
            for (int i = 0; i < 2; i++) {
                uint32_t ad = AH + (wm + i * 16 + aro) * ERS_B + sl * 32 + akq;
                ldm_x4(ah[i], ad);
                ldm_x4(al[i], ad + ETILE_B);
            }
#pragma unroll
            for (int jj = 0; jj < 2; jj++) {
                uint32_t bd = BH + (wn + jj * 16 + bro) * ERS_B + sl * 32 + bkq;
                ldm_x4(bh[jj], bd);
                ldm_x4(bl[jj], bd + ETILE_B);
            }
#pragma unroll
            for (int i = 0; i < 2; i++)
#pragma unroll
                for (int jj = 0; jj < 2; jj++) {
                    mma16(acc[i][2 * jj],     ah[i], bh[jj]);
                    mma16(acc[i][2 * jj + 1], ah[i], bh[jj] + 2);
                }
#pragma unroll
            for (int i = 0; i < 2; i++)
#pragma unroll
                for (int jj = 0; jj < 2; jj++) {
                    mma16(acc[i][2 * jj],     ah[i], bl[jj]);
                    mma16(acc[i][2 * jj + 1], ah[i], bl[jj] + 2);
                }
#pragma unroll
            for (int i = 0; i < 2; i++)
#pragma unroll
                for (int jj = 0; jj < 2; jj++) {
                    mma16(acc[i][2 * jj],     al[i], bh[jj]);
                    mma16(acc[i][2 * jj + 1], al[i], bh[jj] + 2);
                }
        }
        __syncthreads();
        s ^= 1;
    }

    float* E = g_energy + (size_t)b * CCH * CCH;
    const bool mir = (bi != bj);
#pragma unroll
    for (int i = 0; i < 2; i++)
#pragma unroll
        for (int j = 0; j < 4; j++) {
            const int m = m0 + wm + i * 16 + qm;
            const int n = n0 + wn + j * 8 + qp * 2;
            float2 v0 = make_float2(acc[i][j][0], acc[i][j][1]);
            float2 v1 = make_float2(acc[i][j][2], acc[i][j][3]);
            *(float2*)&E[(size_t)m * CCH + n]       = v0;
            *(float2*)&E[(size_t)(m + 8) * CCH + n] = v1;
            if (mir) {
                E[(size_t)n * CCH + m]           = v0.x;
                E[(size_t)(n + 1) * CCH + m]     = v0.y;
                E[(size_t)n * CCH + m + 8]       = v1.x;
                E[(size_t)(n + 1) * CCH + m + 8] = v1.y;
            }
        }
}

// ---------------------------------------------------------------------------
// Kernel 2: softmax of exp(rowmin - e)/sum, write fp16 attention
// ---------------------------------------------------------------------------
__global__ __launch_bounds__(256) void softmax_kernel()
{
    const int row  = blockIdx.x * 8 + (threadIdx.x >> 5);
    const int lane = threadIdx.x & 31;
    const float* e = g_energy + (size_t)row * CCH;
    __half* a = g_attn + (size_t)row * CCH;

    float v[16];
    float mn = 3.4e38f;
#pragma unroll
    for (int i = 0; i < 16; i++) { v[i] = e[lane + i * 32]; mn = fminf(mn, v[i]); }
#pragma unroll
    for (int o = 16; o > 0; o >>= 1)
        mn = fminf(mn, __shfl_xor_sync(0xffffffffu, mn, o));
    float s = 0.f;
#pragma unroll
    for (int i = 0; i < 16; i++) { v[i] = expf(mn - v[i]); s += v[i]; }
#pragma unroll
    for (int o = 16; o > 0; o >>= 1)
        s += __shfl_xor_sync(0xffffffffu, s, o);
    const float r = 1.0f / s;
#pragma unroll
    for (int i = 0; i < 16; i++) a[lane + i * 32] = __float2half_rn(v[i] * r);
}

// ---------------------------------------------------------------------------
// Kernel 3: y[b] = gamma * (attn[b] @ q[b]) + x[b]   (fp16 1-pass)
// BK=64 double-buffered; __launch_bounds__(512, 2) pins 2 CTAs/SM (<=64 regs).
// A = g_attn [128 m x 64 k] row-major (stride 72 fp16); B = qh [64 k x 128 n]
// k-major (stride 136 fp16, ldmatrix.trans). 512 thr, warps 4x4, warp 32x32.
// ---------------------------------------------------------------------------
#define OA_RS_B 144
#define OA_TILE_B (128 * OA_RS_B)        // 18432 B
#define OB_RS_B  272                     // 136 fp16
#define OB_TILE_B (64 * OB_RS_B)         // 17408 B
#define OSTAGE_B (OA_TILE_B + OB_TILE_B) // 35840 B
#define OSMEM_TOTAL (2 * OSTAGE_B)       // 71680 B

__global__ __launch_bounds__(512, 2) void out_kernel(const float* __restrict__ x,
                                                     const float* __restrict__ gamma,
                                                     float* __restrict__ out)
{
    extern __shared__ __align__(256) char smem[];
    const uint32_t sbase = smem_u32(smem);
    const int tid = threadIdx.x, lane = tid & 31, wid = tid >> 5;
    const int b = blockIdx.z;
    const __half* A = g_attn + (size_t)b * CCH * CCH;
    const __half* qh = g_qh + (size_t)b * CCH * NPIX;
    const int m0 = blockIdx.y * 128;
    const int n0 = blockIdx.x * 128;

    const int wm = (wid >> 2) * 32, wn = (wid & 3) * 32;
    const int qm = lane >> 2, qp = lane & 3;

    // copy slots: A 128 rows x 8 chunks = 1024 (2/thread); B 64 rows x 16 = 1024
    const int acr = tid >> 2, acv = (tid & 3) * 2;
    const int bcr = tid >> 3, bcv = (tid & 7) * 2;

    const int aro = lane & 15, akq = (lane >> 4) * 16;
    const int bro = (lane & 7) + 8 * ((lane >> 3) & 1);
    const int bco = 8 * (lane >> 4);

    float acc[2][4][4];
#pragma unroll
    for (int i = 0; i < 2; i++)
#pragma unroll
        for (int j = 0; j < 4; j++)
#pragma unroll
            for (int k = 0; k < 4; k++) acc[i][j][k] = 0.f;

#define O_ISSUE(S, K0)                                                            \
    {                                                                             \
        const uint32_t tb = sbase + (S) * OSTAGE_B;                               \
        const __half* gA = A + (size_t)(m0 + acr) * CCH + (K0);                   \
        const __half* gB = qh + (size_t)((K0) + bcr) * NPIX + n0;                 \
        _Pragma("unroll")                                                         \
        for (int c = 0; c < 2; c++) {                                             \
            cp16(tb + acr * OA_RS_B + (acv + c) * 16, gA + (acv + c) * 8);        \
            cp16(tb + OA_TILE_B + bcr * OB_RS_B + (bcv + c) * 16,                 \
                 gB + (bcv + c) * 8);                                             \
        }                                                                         \
        CP_COMMIT();                                                              \
    }

    O_ISSUE(0, 0);
    int s = 0;
    constexpr int NCH = CCH / 64;   // 8
    for (int it = 0; it < NCH; ++it) {
        if (it + 1 < NCH) { O_ISSUE(s ^ 1, (it + 1) * 64); CP_WAIT(1); }
        else              { CP_WAIT(0); }
        __syncthreads();
        const uint32_t AB = sbase + s * OSTAGE_B;
        const uint32_t BB = AB + OA_TILE_B;
#pragma unroll
        for (int sl = 0; sl < 4; sl++) {
            uint32_t af[2][4], bf[2][4];
#pragma unroll
            for (int i = 0; i < 2; i++)
                ldm_x4(af[i], AB + (wm + i * 16 + aro) * OA_RS_B + sl * 32 + akq);
#pragma unroll
            for (int jj = 0; jj < 2; jj++)
                ldm_x4_t(bf[jj], BB + (sl * 16 + bro) * OB_RS_B
                                    + (wn + jj * 16 + bco) * 2);
#pragma unroll
            for (int i = 0; i < 2; i++)
#pragma unroll
                for (int jj = 0; jj < 2; jj++) {
                    mma16(acc[i][2 * jj],     af[i], bf[jj]);
                    mma16(acc[i][2 * jj + 1], af[i], bf[jj] + 2);
                }
        }
        __syncthreads();
        s ^= 1;
    }

    const float g = *gamma;
#pragma unroll
    for (int i = 0; i < 2; i++)
#pragma unroll
        for (int j = 0; j < 4; j++) {
            const int m = m0 + wm + i * 16 + qm;
            const int n = n0 + wn + j * 8 + qp * 2;
            {
                const size_t p = (size_t)(b * CCH + m) * NPIX + n;
                float2 xv = *(const float2*)(x + p);
                float2 o;
                o.x = fmaf(g, acc[i][j][0], xv.x);
                o.y = fmaf(g, acc[i][j][1], xv.y);
                *(float2*)(out + p) = o;
            }
            {
                const size_t p = (size_t)(b * CCH + m + 8) * NPIX + n;
                float2 xv = *(const float2*)(x + p);
                float2 o;
                o.x = fmaf(g, acc[i][j][2], xv.x);
                o.y = fmaf(g, acc[i][j][3], xv.y);
                *(float2*)(out + p) = o;
            }
        }
}

// ---------------------------------------------------------------------------
extern "C" void kernel_launch(void* const* d_in, const int* in_sizes, int n_in,
                              void* d_out, int out_size)
{
    const float* x     = (const float*)d_in[0];
    const float* gamma = (const float*)d_in[1];
    float* out = (float*)d_out;

    cudaFuncSetAttribute(out_kernel,
                         cudaFuncAttributeMaxDynamicSharedMemorySize, OSMEM_TOTAL);

    split_kernel<<<(unsigned)(NTOT / 4 / 256), 256>>>(x);
    energy_kernel<<<dim3(36, BATCH), 128>>>();
    softmax_kernel<<<(BATCH * CCH) / 8, 256>>>();
    out_kernel<<<dim3(NPIX / 128, CCH / 128, BATCH), 512, OSMEM_TOTAL>>>(x, gamma, out);
}

// round 14
// speedup vs baseline: 1.4387x; 1.0806x over previous
#include <cuda_runtime.h>
#include <cuda_fp16.h>
#include <cstdint>

#define BATCH 16
#define CCH   512
#define NPIX  4096
#define NTOT  ((size_t)BATCH * CCH * NPIX)

// scratch
__device__ float  g_energy[(size_t)BATCH * CCH * CCH];   // 16 MB fp32 energy
__device__ __half g_attn  [(size_t)BATCH * CCH * CCH];   // 8 MB fp16 attention
__device__ __half g_qh[NTOT];                            // 64 MB: rn(q)
__device__ __half g_ql[NTOT];                            // 64 MB: rn(q - qh)

// ---------------------------------------------------------------------------
// PTX helpers (base-ISA sm_75/80 ops, legal under compute_103)
// ---------------------------------------------------------------------------
__device__ __forceinline__ uint32_t smem_u32(const void* p) {
    uint32_t a;
    asm("{ .reg .u64 t; cvta.to.shared.u64 t, %1; cvt.u32.u64 %0, t; }" : "=r"(a) : "l"(p));
    return a;
}
__device__ __forceinline__ void ldm_x4(uint32_t* r, uint32_t addr) {
    asm volatile("ldmatrix.sync.aligned.m8n8.x4.shared.b16 {%0,%1,%2,%3}, [%4];"
        : "=r"(r[0]), "=r"(r[1]), "=r"(r[2]), "=r"(r[3]) : "r"(addr));
}
__device__ __forceinline__ void ldm_x4_t(uint32_t* r, uint32_t addr) {
    asm volatile("ldmatrix.sync.aligned.m8n8.x4.trans.shared.b16 {%0,%1,%2,%3}, [%4];"
        : "=r"(r[0]), "=r"(r[1]), "=r"(r[2]), "=r"(r[3]) : "r"(addr));
}
__device__ __forceinline__ void mma16(float* d, const uint32_t* a, const uint32_t* b) {
    asm volatile(
        "mma.sync.aligned.m16n8k16.row.col.f32.f16.f16.f32 "
        "{%0,%1,%2,%3}, {%4,%5,%6,%7}, {%8,%9}, {%0,%1,%2,%3};"
        : "+f"(d[0]), "+f"(d[1]), "+f"(d[2]), "+f"(d[3])
        : "r"(a[0]), "r"(a[1]), "r"(a[2]), "r"(a[3]), "r"(b[0]), "r"(b[1]));
}
__device__ __forceinline__ void cp16(uint32_t saddr, const void* g) {
    asm volatile("cp.async.cg.shared.global [%0], [%1], 16;" :: "r"(saddr), "l"(g) : "memory");
}
#define CP_COMMIT() asm volatile("cp.async.commit_group;" ::: "memory")
#define CP_WAIT(n)  asm volatile("cp.async.wait_group %0;" :: "n"(n) : "memory")

// ---------------------------------------------------------------------------
// Kernel 0: split q -> qh (rn fp16) + ql (rn residual fp16)
// ---------------------------------------------------------------------------
__global__ __launch_bounds__(256) void split_kernel(const float* __restrict__ x)
{
    size_t i = ((size_t)blockIdx.x * 256 + threadIdx.x) * 4;
    float4 v = *(const float4*)(x + i);
    __half2 h0 = __floats2half2_rn(v.x, v.y);
    __half2 h1 = __floats2half2_rn(v.z, v.w);
    float2 f0 = __half22float2(h0), f1 = __half22float2(h1);
    __half2 l0 = __floats2half2_rn(v.x - f0.x, v.y - f0.y);
    __half2 l1 = __floats2half2_rn(v.z - f1.x, v.w - f1.y);
    *(uint2*)(g_qh + i) = make_uint2(*(uint32_t*)&h0, *(uint32_t*)&h1);
    *(uint2*)(g_ql + i) = make_uint2(*(uint32_t*)&l0, *(uint32_t*)&l1);
}

// ---------------------------------------------------------------------------
// Kernel 1: energy[b] = q qᵀ (3-pass fp16: hh + hl + lh), symmetric 64x64 blocks.
// 128 thr (4 warps 2x2, warp 32x32), BK=32, 2-stage cp.async, ldmatrix.
// Single __syncthreads per iteration (wait -> sync -> issue -> compute).
// ---------------------------------------------------------------------------
#define ERS_B  80                       // row stride bytes
#define ETILE_B (64 * ERS_B)            // 5120 B per tile
#define ESTAGE_B (4 * ETILE_B)          // AH|AL|BH|BL = 20480 B

__global__ __launch_bounds__(128) void energy_kernel()
{
    __shared__ __align__(256) char smem[2 * ESTAGE_B];   // 40 KB
    const uint32_t sbase = smem_u32(smem);
    const int tid = threadIdx.x, lane = tid & 31, wid = tid >> 5;
    const int b = blockIdx.y;

    int bi = 0, t = blockIdx.x, rowlen = 8;
    while (t >= rowlen) { t -= rowlen; bi++; rowlen--; }
    const int bj = bi + t;
    const int m0 = bi * 64, n0 = bj * 64;

    const __half* qh = g_qh + (size_t)b * CCH * NPIX;
    const __half* ql = g_ql + (size_t)b * CCH * NPIX;

    const int wm = (wid >> 1) * 32, wn = (wid & 1) * 32;
    const int qm = lane >> 2, qp = lane & 3;

    float acc[2][4][4];
#pragma unroll
    for (int i = 0; i < 2; i++)
#pragma unroll
        for (int j = 0; j < 4; j++)
#pragma unroll
            for (int k = 0; k < 4; k++) acc[i][j][k] = 0.f;

    // per-thread copy slots: per tile 256 16B-chunks (64 rows x 4), 2 per thread
    const int cr0 = tid >> 2, cv0 = tid & 3;
    const int cr1 = (tid + 128) >> 2, cv1 = tid & 3;

    const int aro = lane & 15, akq = (lane >> 4) * 16;
    const int bro = (lane & 7) + 8 * (lane >> 4);
    const int bkq = ((lane >> 3) & 1) * 16;

#define E_ISSUE(S, K0)                                                           \
    {                                                                            \
        const uint32_t tb = sbase + (S) * ESTAGE_B;                              \
        const __half* sA0 = qh + (size_t)(m0 + cr0) * NPIX + (K0);               \
        const __half* sA1 = qh + (size_t)(m0 + cr1) * NPIX + (K0);               \
        cp16(tb + cr0 * ERS_B + cv0 * 16, sA0 + cv0 * 8);                        \
        cp16(tb + cr1 * ERS_B + cv1 * 16, sA1 + cv1 * 8);                        \
        const __half* lA0 = ql + (size_t)(m0 + cr0) * NPIX + (K0);               \
        const __half* lA1 = ql + (size_t)(m0 + cr1) * NPIX + (K0);               \
        cp16(tb + ETILE_B + cr0 * ERS_B + cv0 * 16, lA0 + cv0 * 8);              \
        cp16(tb + ETILE_B + cr1 * ERS_B + cv1 * 16, lA1 + cv1 * 8);              \
        const __half* sB0 = qh + (size_t)(n0 + cr0) * NPIX + (K0);               \
        const __half* sB1 = qh + (size_t)(n0 + cr1) * NPIX + (K0);               \
        cp16(tb + 2 * ETILE_B + cr0 * ERS_B + cv0 * 16, sB0 + cv0 * 8);          \
        cp16(tb + 2 * ETILE_B + cr1 * ERS_B + cv1 * 16, sB1 + cv1 * 8);          \
        const __half* lB0 = ql + (size_t)(n0 + cr0) * NPIX + (K0);               \
        const __half* lB1 = ql + (size_t)(n0 + cr1) * NPIX + (K0);               \
        cp16(tb + 3 * ETILE_B + cr0 * ERS_B + cv0 * 16, lB0 + cv0 * 8);          \
        cp16(tb + 3 * ETILE_B + cr1 * ERS_B + cv1 * 16, lB1 + cv1 * 8);          \
        CP_COMMIT();                                                             \
    }

    E_ISSUE(0, 0);
    int s = 0;
    constexpr int NCH = NPIX / 32;   // 128
    for (int it = 0; it < NCH; ++it) {
        CP_WAIT(0);
        __syncthreads();
        if (it + 1 < NCH) E_ISSUE(s ^ 1, (it + 1) * 32);
        const uint32_t AH = sbase + s * ESTAGE_B;
        const uint32_t BH = AH + 2 * ETILE_B;
#pragma unroll
        for (int sl = 0; sl < 2; sl++) {
            uint32_t ah[2][4], al[2][4], bh[2][4], bl[2][4];
#pragma unroll
            for (int i = 0; i < 2; i++) {
                uint32_t ad = AH + (wm + i * 16 + aro) * ERS_B + sl * 32 + akq;
                ldm_x4(ah[i], ad);
                ldm_x4(al[i], ad + ETILE_B);
            }
#pragma unroll
            for (int jj = 0; jj < 2; jj++) {
                uint32_t bd = BH + (wn + jj * 16 + bro) * ERS_B + sl * 32 + bkq;
                ldm_x4(bh[jj], bd);
                ldm_x4(bl[jj], bd + ETILE_B);
            }
#pragma unroll
            for (int i = 0; i < 2; i++)
#pragma unroll
                for (int jj = 0; jj < 2; jj++) {
                    mma16(acc[i][2 * jj],     ah[i], bh[jj]);
                    mma16(acc[i][2 * jj + 1], ah[i], bh[jj] + 2);
                }
#pragma unroll
            for (int i = 0; i < 2; i++)
#pragma unroll
                for (int jj = 0; jj < 2; jj++) {
                    mma16(acc[i][2 * jj],     ah[i], bl[jj]);
                    mma16(acc[i][2 * jj + 1], ah[i], bl[jj] + 2);
                }
#pragma unroll
            for (int i = 0; i < 2; i++)
#pragma unroll
                for (int jj = 0; jj < 2; jj++) {
                    mma16(acc[i][2 * jj],     al[i], bh[jj]);
                    mma16(acc[i][2 * jj + 1], al[i], bh[jj] + 2);
                }
        }
        s ^= 1;
    }

    float* E = g_energy + (size_t)b * CCH * CCH;
    const bool mir = (bi != bj);
#pragma unroll
    for (int i = 0; i < 2; i++)
#pragma unroll
        for (int j = 0; j < 4; j++) {
            const int m = m0 + wm + i * 16 + qm;
            const int n = n0 + wn + j * 8 + qp * 2;
            float2 v0 = make_float2(acc[i][j][0], acc[i][j][1]);
            float2 v1 = make_float2(acc[i][j][2], acc[i][j][3]);
            *(float2*)&E[(size_t)m * CCH + n]       = v0;
            *(float2*)&E[(size_t)(m + 8) * CCH + n] = v1;
            if (mir) {
                E[(size_t)n * CCH + m]           = v0.x;
                E[(size_t)(n + 1) * CCH + m]     = v0.y;
                E[(size_t)n * CCH + m + 8]       = v1.x;
                E[(size_t)(n + 1) * CCH + m + 8] = v1.y;
            }
        }
}

// ---------------------------------------------------------------------------
// Kernel 2: softmax of exp(rowmin - e)/sum, write fp16 attention
// ---------------------------------------------------------------------------
__global__ __launch_bounds__(256) void softmax_kernel()
{
    const int row  = blockIdx.x * 8 + (threadIdx.x >> 5);
    const int lane = threadIdx.x & 31;
    const float* e = g_energy + (size_t)row * CCH;
    __half* a = g_attn + (size_t)row * CCH;

    float v[16];
    float mn = 3.4e38f;
#pragma unroll
    for (int i = 0; i < 16; i++) { v[i] = e[lane + i * 32]; mn = fminf(mn, v[i]); }
#pragma unroll
    for (int o = 16; o > 0; o >>= 1)
        mn = fminf(mn, __shfl_xor_sync(0xffffffffu, mn, o));
    float s = 0.f;
#pragma unroll
    for (int i = 0; i < 16; i++) { v[i] = expf(mn - v[i]); s += v[i]; }
#pragma unroll
    for (int o = 16; o > 0; o >>= 1)
        s += __shfl_xor_sync(0xffffffffu, s, o);
    const float r = 1.0f / s;
#pragma unroll
    for (int i = 0; i < 16; i++) a[lane + i * 32] = __float2half_rn(v[i] * r);
}

// ---------------------------------------------------------------------------
// Kernel 3: y[b] = gamma * (attn[b] @ q[b]) + x[b]   (fp16 1-pass)
// BK=32, 3-stage cp.async ring (prefetch depth 2), single sync per iteration.
// A = g_attn [128 m x 32 k] row-major (stride 40 fp16); B = qh [32 k x 128 n]
// k-major (stride 136 fp16, ldmatrix.trans). 512 thr, warps 4x4, warp 32x32.
// ---------------------------------------------------------------------------
#define OA_RS_B 80
#define OA_TILE_B (128 * OA_RS_B)        // 10240 B
#define OB_RS_B  272                     // 136 fp16
#define OB_TILE_B (32 * OB_RS_B)         // 8704 B
#define OSTAGE_B (OA_TILE_B + OB_TILE_B) // 18944 B
#define OSMEM_TOTAL (3 * OSTAGE_B)       // 56832 B

__global__ __launch_bounds__(512, 2) void out_kernel(const float* __restrict__ x,
                                                     const float* __restrict__ gamma,
                                                     float* __restrict__ out)
{
    extern __shared__ __align__(256) char smem[];
    const uint32_t sbase = smem_u32(smem);
    const int tid = threadIdx.x, lane = tid & 31, wid = tid >> 5;
    const int b = blockIdx.z;
    const __half* A = g_attn + (size_t)b * CCH * CCH;
    const __half* qh = g_qh + (size_t)b * CCH * NPIX;
    const int m0 = blockIdx.y * 128;
    const int n0 = blockIdx.x * 128;

    const int wm = (wid >> 2) * 32, wn = (wid & 3) * 32;
    const int qm = lane >> 2, qp = lane & 3;

    // copy slots: A 128 rows x 4 chunks = 512 (1/thread); B 32 rows x 16 = 512
    const int acr = tid >> 2, acv = tid & 3;
    const int bcr = tid >> 4, bcv = tid & 15;

    const int aro = lane & 15, akq = (lane >> 4) * 16;
    const int bro = (lane & 7) + 8 * ((lane >> 3) & 1);
    const int bco = 8 * (lane >> 4);

    float acc[2][4][4];
#pragma unroll
    for (int i = 0; i < 2; i++)
#pragma unroll
        for (int j = 0; j < 4; j++)
#pragma unroll
            for (int k = 0; k < 4; k++) acc[i][j][k] = 0.f;

#define O_ISSUE(S, K0)                                                            \
    {                                                                             \
        const uint32_t tb = sbase + (S) * OSTAGE_B;                               \
        cp16(tb + acr * OA_RS_B + acv * 16,                                       \
             A + (size_t)(m0 + acr) * CCH + (K0) + acv * 8);                      \
        cp16(tb + OA_TILE_B + bcr * OB_RS_B + bcv * 16,                           \
             qh + (size_t)((K0) + bcr) * NPIX + n0 + bcv * 8);                    \
        CP_COMMIT();                                                              \
    }

    O_ISSUE(0, 0);
    O_ISSUE(1, 32);
    int st_r = 0, st_w = 2;
    constexpr int NCH = CCH / 32;   // 16
    for (int it = 0; it < NCH; ++it) {
        if (it + 1 < NCH) { CP_WAIT(1); } else { CP_WAIT(0); }
        __syncthreads();
        if (it + 2 < NCH) {
            O_ISSUE(st_w, (it + 2) * 32);
            st_w = (st_w == 2) ? 0 : st_w + 1;
        }
        const uint32_t AB = sbase + st_r * OSTAGE_B;
        const uint32_t BB = AB + OA_TILE_B;
#pragma unroll
        for (int sl = 0; sl < 2; sl++) {
            uint32_t af[2][4], bf[2][4];
#pragma unroll
            for (int i = 0; i < 2; i++)
                ldm_x4(af[i], AB + (wm + i * 16 + aro) * OA_RS_B + sl * 32 + akq);
#pragma unroll
            for (int jj = 0; jj < 2; jj++)
                ldm_x4_t(bf[jj], BB + (sl * 16 + bro) * OB_RS_B
                                    + (wn + jj * 16 + bco) * 2);
#pragma unroll
            for (int i = 0; i < 2; i++)
#pragma unroll
                for (int jj = 0; jj < 2; jj++) {
                    mma16(acc[i][2 * jj],     af[i], bf[jj]);
                    mma16(acc[i][2 * jj + 1], af[i], bf[jj] + 2);
                }
        }
        st_r = (st_r == 2) ? 0 : st_r + 1;
    }

    const float g = *gamma;
#pragma unroll
    for (int i = 0; i < 2; i++)
#pragma unroll
        for (int j = 0; j < 4; j++) {
            const int m = m0 + wm + i * 16 + qm;
            const int n = n0 + wn + j * 8 + qp * 2;
            {
                const size_t p = (size_t)(b * CCH + m) * NPIX + n;
                float2 xv = *(const float2*)(x + p);
                float2 o;
                o.x = fmaf(g, acc[i][j][0], xv.x);
                o.y = fmaf(g, acc[i][j][1], xv.y);
                *(float2*)(out + p) = o;
            }
            {
                const size_t p = (size_t)(b * CCH + m + 8) * NPIX + n;
                float2 xv = *(const float2*)(x + p);
                float2 o;
                o.x = fmaf(g, acc[i][j][2], xv.x);
                o.y = fmaf(g, acc[i][j][3], xv.y);
                *(float2*)(out + p) = o;
            }
        }
}

// ---------------------------------------------------------------------------
extern "C" void kernel_launch(void* const* d_in, const int* in_sizes, int n_in,
                              void* d_out, int out_size)
{
    const float* x     = (const float*)d_in[0];
    const float* gamma = (const float*)d_in[1];
    float* out = (float*)d_out;

    cudaFuncSetAttribute(out_kernel,
                         cudaFuncAttributeMaxDynamicSharedMemorySize, OSMEM_TOTAL);

    split_kernel<<<(unsigned)(NTOT / 4 / 256), 256>>>(x);
    energy_kernel<<<dim3(36, BATCH), 128>>>();
    softmax_kernel<<<(BATCH * CCH) / 8, 256>>>();
    out_kernel<<<dim3(NPIX / 128, CCH / 128, BATCH), 512, OSMEM_TOTAL>>>(x, gamma, out);
}